// round 8
// baseline (speedup 1.0000x reference)
#include <cuda_runtime.h>
#include <cuda_fp16.h>
#include <math.h>
#include <stdint.h>

// Scratch (static device arrays — no allocation allowed)
#define NMAX 100000
#define EMAX 1600000
#define DIM  64

// Per-node src record, interleaved at half2 granularity:
//   g_s[n*128 + 4*lane + {0,1}] = u cols (2*lane, 2*lane+1)   (u = x@W1a + b1)
//   g_s[n*128 + 4*lane + {2,3}] = xt cols (2*lane, 2*lane+1)  (xt = x@wt + bt)
// -> one uint2 load per lane fetches both u and xt pairs.
__device__ __half g_s[NMAX * 2 * DIM];
// Per-node dst record: v = x@W1b, 64 halfs.
__device__ __half g_d[NMAX * DIM];
// pos packed as float4 for single-LDG broadcast loads
__device__ float4 g_pos4[NMAX];
// CSR build
__device__ int g_cnt[NMAX];
__device__ int g_off[NMAX];
__device__ int g_cur[NMAX];
__device__ int g_bsum[128];
__device__ int g_perm[EMAX];

// ---------------------------------------------------------------------------
// Per-node precompute (fp32 math, fp16 storage).
// ---------------------------------------------------------------------------
__global__ void node_kernel(const float* __restrict__ x,
                            const float* __restrict__ w1,
                            const float* __restrict__ b1,
                            const float* __restrict__ wt,
                            const float* __restrict__ bt,
                            int N) {
    __shared__ float sA[DIM * DIM];   // w1 rows 0..63
    __shared__ float sB[DIM * DIM];   // w1 rows 64..127
    __shared__ float sT[DIM * DIM];   // wt
    __shared__ float sb1[DIM], sbt[DIM];

    int tid = threadIdx.x;
    for (int i = tid; i < DIM * DIM; i += blockDim.x) {
        sA[i] = w1[i];
        sB[i] = w1[DIM * DIM + i];
        sT[i] = wt[i];
    }
    if (tid < DIM) { sb1[tid] = b1[tid]; sbt[tid] = bt[tid]; }
    __syncthreads();

    const int lane   = tid & 31;
    const int warp   = (blockIdx.x * blockDim.x + tid) >> 5;
    const int nwarps = (gridDim.x * blockDim.x) >> 5;
    const int NP = 4;

    float2 bb1 = *(const float2*)&sb1[2 * lane];
    float2 bbt = *(const float2*)&sbt[2 * lane];

    for (int n0 = warp * NP; n0 < N; n0 += nwarps * NP) {
        int cnt = N - n0; if (cnt > NP) cnt = NP;

        float xa[NP], xb[NP];
        #pragma unroll
        for (int j = 0; j < NP; j++) {
            int n = n0 + j;
            if (j < cnt) {
                xa[j] = x[(size_t)n * DIM + lane];
                xb[j] = x[(size_t)n * DIM + 32 + lane];
            } else { xa[j] = 0.f; xb[j] = 0.f; }
        }

        float2 au[NP], av[NP], at[NP];
        #pragma unroll
        for (int j = 0; j < NP; j++) {
            au[j] = bb1;
            av[j] = make_float2(0.f, 0.f);
            at[j] = bbt;
        }

        #pragma unroll 4
        for (int k = 0; k < DIM; k++) {
            float2 wa  = *(const float2*)&sA[k * DIM + 2 * lane];
            float2 wb  = *(const float2*)&sB[k * DIM + 2 * lane];
            float2 wt2 = *(const float2*)&sT[k * DIM + 2 * lane];
            #pragma unroll
            for (int j = 0; j < NP; j++) {
                float xk = (k < 32) ? __shfl_sync(0xffffffffu, xa[j], k)
                                    : __shfl_sync(0xffffffffu, xb[j], k - 32);
                au[j].x = fmaf(xk, wa.x,  au[j].x);
                au[j].y = fmaf(xk, wa.y,  au[j].y);
                av[j].x = fmaf(xk, wb.x,  av[j].x);
                av[j].y = fmaf(xk, wb.y,  av[j].y);
                at[j].x = fmaf(xk, wt2.x, at[j].x);
                at[j].y = fmaf(xk, wt2.y, at[j].y);
            }
        }

        #pragma unroll
        for (int j = 0; j < NP; j++) {
            if (j < cnt) {
                size_t n = (size_t)(n0 + j);
                __half2 hu = __float22half2_rn(au[j]);
                __half2 hx = __float22half2_rn(at[j]);
                uint2 pk;
                pk.x = *(const unsigned int*)&hu;
                pk.y = *(const unsigned int*)&hx;
                *(uint2*)&g_s[n * 2 * DIM + 4 * lane] = pk;
                *(__half2*)&g_d[n * DIM + 2 * lane]   = __float22half2_rn(av[j]);
            }
        }
    }
}

// ---------------------------------------------------------------------------
__global__ void pos4_kernel(const float* __restrict__ pos, int N) {
    int i = blockIdx.x * blockDim.x + threadIdx.x;
    if (i < N)
        g_pos4[i] = make_float4(pos[3 * i], pos[3 * i + 1], pos[3 * i + 2], 0.f);
}

// ---------------------------------------------------------------------------
// CSR build: histogram -> scan -> scatter
// ---------------------------------------------------------------------------
__global__ void hist_kernel(const int* __restrict__ ei, int E) {
    int i = blockIdx.x * blockDim.x + threadIdx.x;
    if (i < E) atomicAdd(&g_cnt[ei[E + i]], 1);
}

__global__ void scan_local(int N) {
    __shared__ int sh[1024];
    int t = threadIdx.x;
    int i = blockIdx.x * 1024 + t;
    int v = (i < N) ? g_cnt[i] : 0;
    sh[t] = v;
    __syncthreads();
    #pragma unroll
    for (int o = 1; o < 1024; o <<= 1) {
        int a = (t >= o) ? sh[t - o] : 0;
        __syncthreads();
        sh[t] += a;
        __syncthreads();
    }
    if (i < N) g_off[i] = sh[t] - v;       // exclusive
    if (t == 1023) g_bsum[blockIdx.x] = sh[t];
}

__global__ void scan_blocks(int nb) {
    __shared__ int sh[128];
    int t = threadIdx.x;
    int v = (t < nb) ? g_bsum[t] : 0;
    sh[t] = v;
    __syncthreads();
    #pragma unroll
    for (int o = 1; o < 128; o <<= 1) {
        int a = (t >= o) ? sh[t - o] : 0;
        __syncthreads();
        sh[t] += a;
        __syncthreads();
    }
    if (t < nb) g_bsum[t] = sh[t] - v;     // exclusive
}

__global__ void scan_add(int N) {
    int i = blockIdx.x * blockDim.x + threadIdx.x;
    if (i < N) {
        int v = g_off[i] + g_bsum[i >> 10];
        g_off[i] = v;
        g_cur[i] = v;
    }
}

__global__ void scatter_kernel(const int* __restrict__ ei, int E) {
    int i = blockIdx.x * blockDim.x + threadIdx.x;
    if (i < E) {
        int d = ei[E + i];
        int p = atomicAdd(&g_cur[d], 1);
        g_perm[p] = i;
    }
}

// ---------------------------------------------------------------------------
// Aggregate: one warp per dst node. Lane owns cols (2*lane, 2*lane+1).
// v[dst], pos[dst] loaded once; per edge: one uint2 gather (u+xt), weight via
// warp-reduced dot, ew[e] store, register accumulate; one plain store per dst.
// ---------------------------------------------------------------------------
__global__ void agg_kernel(const int* __restrict__ ei,
                           const float* __restrict__ w1,
                           const float* __restrict__ w2,
                           const float* __restrict__ b2p,
                           float* __restrict__ out,
                           float* __restrict__ ew,
                           int N, int E) {
    const int lane   = threadIdx.x & 31;
    const int warp   = (blockIdx.x * blockDim.x + threadIdx.x) >> 5;
    const int nwarps = (gridDim.x * blockDim.x) >> 5;

    const float2 wc  = *(const float2*)&w1[128 * DIM + 2 * lane];
    const float2 w2v = *(const float2*)&w2[2 * lane];
    const float  b2  = b2p[0];

    for (int d = warp; d < N; d += nwarps) {
        float4 pd = g_pos4[d];
        float2 v2 = __half22float2(*(const __half2*)&g_d[(size_t)d * DIM + 2 * lane]);

        float2 acc = make_float2(0.f, 0.f);
        int st = g_off[d];
        int en = st + g_cnt[d];

        for (int i = st; i < en; i++) {
            int e = g_perm[i];
            int s = ei[e];

            float4 ps = g_pos4[s];
            float dx = ps.x - pd.x, dy = ps.y - pd.y, dz = ps.z - pd.z;
            float len = sqrtf(dx * dx + dy * dy + dz * dz);

            uint2 raw = *(const uint2*)&g_s[(size_t)s * 2 * DIM + 4 * lane];
            float2 u2 = __half22float2(*(const __half2*)&raw.x);
            float2 x2 = __half22float2(*(const __half2*)&raw.y);

            float h0 = fmaxf(fmaf(len, wc.x, u2.x + v2.x), 0.f);
            float h1 = fmaxf(fmaf(len, wc.y, u2.y + v2.y), 0.f);
            float p  = fmaf(h0, w2v.x, h1 * w2v.y);

            #pragma unroll
            for (int o = 16; o > 0; o >>= 1)
                p += __shfl_xor_sync(0xffffffffu, p, o);

            float w = 1.f / (1.f + __expf(-(p + b2)));

            if (lane == 0 && ew) ew[e] = w;

            acc.x = fmaf(x2.x, w, acc.x);
            acc.y = fmaf(x2.y, w, acc.y);
        }

        *(float2*)&out[(size_t)d * DIM + 2 * lane] = acc;
    }
}

// ---------------------------------------------------------------------------
extern "C" void kernel_launch(void* const* d_in, const int* in_sizes, int n_in,
                              void* d_out, int out_size) {
    const float* x   = (const float*)d_in[0];
    const int*   ei  = (const int*)d_in[1];    // int32 (JAX x64 disabled)
    const float* pos = (const float*)d_in[2];
    const float* w1  = (const float*)d_in[3];
    const float* b1  = (const float*)d_in[4];
    const float* w2  = (const float*)d_in[5];
    const float* b2  = (const float*)d_in[6];
    const float* wt  = (const float*)d_in[7];
    const float* bt  = (const float*)d_in[8];

    int N = in_sizes[0] / DIM;   // 100000
    int E = in_sizes[1] / 2;     // 1600000

    float* out = (float*)d_out;
    float* ew  = (out_size >= N * DIM + E) ? out + (size_t)N * DIM : nullptr;

    void* cnt_ptr = nullptr;
    cudaGetSymbolAddress(&cnt_ptr, g_cnt);
    cudaMemsetAsync(cnt_ptr, 0, (size_t)N * sizeof(int));

    node_kernel<<<592, 256>>>(x, w1, b1, wt, bt, N);
    pos4_kernel<<<(N + 255) / 256, 256>>>(pos, N);
    hist_kernel<<<(E + 255) / 256, 256>>>(ei, E);

    int nb = (N + 1023) / 1024;               // 98 blocks (<=128)
    scan_local<<<nb, 1024>>>(N);
    scan_blocks<<<1, 128>>>(nb);
    scan_add<<<(N + 255) / 256, 256>>>(N);

    scatter_kernel<<<(E + 255) / 256, 256>>>(ei, E);

    agg_kernel<<<(N * 32 + 255) / 256, 256>>>(ei, w1, w2, b2, out, ew, N, E);
}

// round 9
// speedup vs baseline: 1.3635x; 1.3635x over previous
#include <cuda_runtime.h>
#include <cuda_fp16.h>
#include <math.h>
#include <stdint.h>

// Scratch (static device arrays — no allocation allowed)
#define NMAX 100000
#define EMAX 1600000
#define DIM  64

__device__ __half g_u [NMAX * DIM];   // u  = x@W1a + b1 (fp16)
__device__ __half g_v [NMAX * DIM];   // v  = x@W1b      (fp16)
__device__ __half g_xt[NMAX * DIM];   // xt = x@wt + bt  (fp16)
__device__ float4 g_pos4[NMAX];
// CSR
__device__ int   g_cnt[NMAX];
__device__ int   g_off[NMAX];
__device__ int   g_cur[NMAX];
__device__ int   g_bsum[128];
__device__ int   g_psrc[EMAX];        // src node per CSR slot
__device__ float g_pw[EMAX];          // edge weight per CSR slot

// ---------------------------------------------------------------------------
// Per-node precompute (fp32 math, fp16 storage).
// ---------------------------------------------------------------------------
__global__ void node_kernel(const float* __restrict__ x,
                            const float* __restrict__ w1,
                            const float* __restrict__ b1,
                            const float* __restrict__ wt,
                            const float* __restrict__ bt,
                            int N) {
    __shared__ float sA[DIM * DIM];   // w1 rows 0..63
    __shared__ float sB[DIM * DIM];   // w1 rows 64..127
    __shared__ float sT[DIM * DIM];   // wt
    __shared__ float sb1[DIM], sbt[DIM];

    int tid = threadIdx.x;
    for (int i = tid; i < DIM * DIM; i += blockDim.x) {
        sA[i] = w1[i];
        sB[i] = w1[DIM * DIM + i];
        sT[i] = wt[i];
    }
    if (tid < DIM) { sb1[tid] = b1[tid]; sbt[tid] = bt[tid]; }
    __syncthreads();

    const int lane   = tid & 31;
    const int warp   = (blockIdx.x * blockDim.x + tid) >> 5;
    const int nwarps = (gridDim.x * blockDim.x) >> 5;
    const int NP = 4;

    float2 bb1 = *(const float2*)&sb1[2 * lane];
    float2 bbt = *(const float2*)&sbt[2 * lane];

    for (int n0 = warp * NP; n0 < N; n0 += nwarps * NP) {
        int cnt = N - n0; if (cnt > NP) cnt = NP;

        float xa[NP], xb[NP];
        #pragma unroll
        for (int j = 0; j < NP; j++) {
            int n = n0 + j;
            if (j < cnt) {
                xa[j] = x[(size_t)n * DIM + lane];
                xb[j] = x[(size_t)n * DIM + 32 + lane];
            } else { xa[j] = 0.f; xb[j] = 0.f; }
        }

        float2 au[NP], av[NP], at[NP];
        #pragma unroll
        for (int j = 0; j < NP; j++) {
            au[j] = bb1;
            av[j] = make_float2(0.f, 0.f);
            at[j] = bbt;
        }

        #pragma unroll 4
        for (int k = 0; k < DIM; k++) {
            float2 wa  = *(const float2*)&sA[k * DIM + 2 * lane];
            float2 wb  = *(const float2*)&sB[k * DIM + 2 * lane];
            float2 wt2 = *(const float2*)&sT[k * DIM + 2 * lane];
            #pragma unroll
            for (int j = 0; j < NP; j++) {
                float xk = (k < 32) ? __shfl_sync(0xffffffffu, xa[j], k)
                                    : __shfl_sync(0xffffffffu, xb[j], k - 32);
                au[j].x = fmaf(xk, wa.x,  au[j].x);
                au[j].y = fmaf(xk, wa.y,  au[j].y);
                av[j].x = fmaf(xk, wb.x,  av[j].x);
                av[j].y = fmaf(xk, wb.y,  av[j].y);
                at[j].x = fmaf(xk, wt2.x, at[j].x);
                at[j].y = fmaf(xk, wt2.y, at[j].y);
            }
        }

        #pragma unroll
        for (int j = 0; j < NP; j++) {
            if (j < cnt) {
                size_t n = (size_t)(n0 + j);
                *(__half2*)&g_u [n * DIM + 2 * lane] = __float22half2_rn(au[j]);
                *(__half2*)&g_v [n * DIM + 2 * lane] = __float22half2_rn(av[j]);
                *(__half2*)&g_xt[n * DIM + 2 * lane] = __float22half2_rn(at[j]);
            }
        }
    }
}

// ---------------------------------------------------------------------------
__global__ void pos4_kernel(const float* __restrict__ pos, int N) {
    int i = blockIdx.x * blockDim.x + threadIdx.x;
    if (i < N)
        g_pos4[i] = make_float4(pos[3 * i], pos[3 * i + 1], pos[3 * i + 2], 0.f);
}

// ---------------------------------------------------------------------------
// CSR counts: histogram -> scan
// ---------------------------------------------------------------------------
__global__ void hist_kernel(const int* __restrict__ ei, int E) {
    int i = blockIdx.x * blockDim.x + threadIdx.x;
    if (i < E) atomicAdd(&g_cnt[ei[E + i]], 1);
}

__global__ void scan_local(int N) {
    __shared__ int sh[1024];
    int t = threadIdx.x;
    int i = blockIdx.x * 1024 + t;
    int v = (i < N) ? g_cnt[i] : 0;
    sh[t] = v;
    __syncthreads();
    #pragma unroll
    for (int o = 1; o < 1024; o <<= 1) {
        int a = (t >= o) ? sh[t - o] : 0;
        __syncthreads();
        sh[t] += a;
        __syncthreads();
    }
    if (i < N) g_off[i] = sh[t] - v;       // exclusive
    if (t == 1023) g_bsum[blockIdx.x] = sh[t];
}

__global__ void scan_blocks(int nb) {
    __shared__ int sh[128];
    int t = threadIdx.x;
    int v = (t < nb) ? g_bsum[t] : 0;
    sh[t] = v;
    __syncthreads();
    #pragma unroll
    for (int o = 1; o < 128; o <<= 1) {
        int a = (t >= o) ? sh[t - o] : 0;
        __syncthreads();
        sh[t] += a;
        __syncthreads();
    }
    if (t < nb) g_bsum[t] = sh[t] - v;     // exclusive
}

__global__ void scan_add(int N) {
    int i = blockIdx.x * blockDim.x + threadIdx.x;
    if (i < N) {
        int v = g_off[i] + g_bsum[i >> 10];
        g_off[i] = v;
        g_cur[i] = v;
    }
}

// ---------------------------------------------------------------------------
// Edge-parallel: compute w = sigmoid(relu(u[s]+v[d]+len*wc) . w2 + b2),
// write ew[e], and scatter (src, w) into the CSR slot of dst.
// HALF-warp per edge; lane sub (0..15) owns cols 4*sub..4*sub+3.
// NO fp32 atomics — only one int cursor atomic per edge.
// ---------------------------------------------------------------------------
__global__ void edge_kernel(const int* __restrict__ ei,
                            const float* __restrict__ w1,
                            const float* __restrict__ w2,
                            const float* __restrict__ b2p,
                            float* __restrict__ ew,
                            int E) {
    const int lane   = threadIdx.x & 31;
    const int half   = lane >> 4;
    const int sub    = lane & 15;
    const int warp   = (blockIdx.x * blockDim.x + threadIdx.x) >> 5;
    const int nwarps = (gridDim.x * blockDim.x) >> 5;

    const float4 wc  = *(const float4*)&w1[128 * DIM + 4 * sub];
    const float4 w2v = *(const float4*)&w2[4 * sub];
    const float  b2  = b2p[0];

    for (int e0 = warp * 2; e0 < E; e0 += nwarps * 2) {
        int e = e0 + half;
        bool valid = (e < E);
        int s = valid ? ei[e]     : 0;
        int d = valid ? ei[E + e] : 0;

        float4 ps = g_pos4[s];
        float4 pd = g_pos4[d];
        float dx = pd.x - ps.x, dy = pd.y - ps.y, dz = pd.z - ps.z;
        float len = sqrtf(dx * dx + dy * dy + dz * dz);

        uint2 uraw = *(const uint2*)&g_u[(size_t)s * DIM + 4 * sub];
        uint2 vraw = *(const uint2*)&g_v[(size_t)d * DIM + 4 * sub];
        float2 u0 = __half22float2(*(const __half2*)&uraw.x);
        float2 u1 = __half22float2(*(const __half2*)&uraw.y);
        float2 v0 = __half22float2(*(const __half2*)&vraw.x);
        float2 v1 = __half22float2(*(const __half2*)&vraw.y);

        float h0 = fmaxf(fmaf(len, wc.x, u0.x + v0.x), 0.f);
        float h1 = fmaxf(fmaf(len, wc.y, u0.y + v0.y), 0.f);
        float h2 = fmaxf(fmaf(len, wc.z, u1.x + v1.x), 0.f);
        float h3 = fmaxf(fmaf(len, wc.w, u1.y + v1.y), 0.f);
        float p  = fmaf(h0, w2v.x, fmaf(h1, w2v.y, fmaf(h2, w2v.z, h3 * w2v.w)));

        #pragma unroll
        for (int o = 8; o > 0; o >>= 1)
            p += __shfl_xor_sync(0xffffffffu, p, o);

        float w = 1.f / (1.f + __expf(-(p + b2)));

        if (valid && sub == 0) {
            if (ew) ew[e] = w;
            int slot = atomicAdd(&g_cur[d], 1);
            g_psrc[slot] = s;
            g_pw[slot]   = w;
        }
    }
}

// ---------------------------------------------------------------------------
// Aggregate: one warp per dst. Lane owns cols (2*lane, 2*lane+1).
// Per edge: broadcast psrc/pw (L1-amortized) + one 4B xt gather per lane +
// 2 FMAs. No shuffle chain; unroll-4 for MLP. One plain store per dst.
// ---------------------------------------------------------------------------
__global__ void agg_kernel(float* __restrict__ out, int N) {
    const int lane   = threadIdx.x & 31;
    const int warp   = (blockIdx.x * blockDim.x + threadIdx.x) >> 5;
    const int nwarps = (gridDim.x * blockDim.x) >> 5;

    for (int d = warp; d < N; d += nwarps) {
        int st = g_off[d];
        int en = st + g_cnt[d];

        float2 acc = make_float2(0.f, 0.f);

        #pragma unroll 4
        for (int i = st; i < en; i++) {
            int   s = g_psrc[i];
            float w = g_pw[i];
            float2 x2 = __half22float2(*(const __half2*)&g_xt[(size_t)s * DIM + 2 * lane]);
            acc.x = fmaf(x2.x, w, acc.x);
            acc.y = fmaf(x2.y, w, acc.y);
        }

        *(float2*)&out[(size_t)d * DIM + 2 * lane] = acc;
    }
}

// ---------------------------------------------------------------------------
extern "C" void kernel_launch(void* const* d_in, const int* in_sizes, int n_in,
                              void* d_out, int out_size) {
    const float* x   = (const float*)d_in[0];
    const int*   ei  = (const int*)d_in[1];    // int32 (JAX x64 disabled)
    const float* pos = (const float*)d_in[2];
    const float* w1  = (const float*)d_in[3];
    const float* b1  = (const float*)d_in[4];
    const float* w2  = (const float*)d_in[5];
    const float* b2  = (const float*)d_in[6];
    const float* wt  = (const float*)d_in[7];
    const float* bt  = (const float*)d_in[8];

    int N = in_sizes[0] / DIM;   // 100000
    int E = in_sizes[1] / 2;     // 1600000

    float* out = (float*)d_out;
    float* ew  = (out_size >= N * DIM + E) ? out + (size_t)N * DIM : nullptr;

    void* cnt_ptr = nullptr;
    cudaGetSymbolAddress(&cnt_ptr, g_cnt);
    cudaMemsetAsync(cnt_ptr, 0, (size_t)N * sizeof(int));

    node_kernel<<<592, 256>>>(x, w1, b1, wt, bt, N);
    pos4_kernel<<<(N + 255) / 256, 256>>>(pos, N);
    hist_kernel<<<(E + 255) / 256, 256>>>(ei, E);

    int nb = (N + 1023) / 1024;
    scan_local<<<nb, 1024>>>(N);
    scan_blocks<<<1, 128>>>(nb);
    scan_add<<<(N + 255) / 256, 256>>>(N);

    edge_kernel<<<2368, 256>>>(ei, w1, w2, b2, ew, E);
    agg_kernel<<<(N * 32 + 255) / 256, 256>>>(out, N);
}

// round 10
// speedup vs baseline: 1.7088x; 1.2533x over previous
#include <cuda_runtime.h>
#include <cuda_fp16.h>
#include <math.h>
#include <stdint.h>

// Scratch (static device arrays — no allocation allowed)
#define NMAX 100000
#define DIM  64

// Packed per-node src record, 128 halfs (256 B):
//   for sub in 0..15: halfs [8*sub .. 8*sub+3] = u cols 4sub..4sub+3
//                     halfs [8*sub+4 .. 8*sub+7] = xt cols 4sub..4sub+3
// -> ONE uint4 (LDG.128) per lane fetches u pair-of-pairs AND xt.
__device__ __half g_p[NMAX * 2 * DIM];
// Per-node dst record: v = x@W1b, 64 halfs (128 B).
__device__ __half g_d[NMAX * DIM];
// pos packed as float4 -> single-wavefront broadcast loads
__device__ float4 g_pos4[NMAX];

// ---------------------------------------------------------------------------
// Zero the node-output region (d_out is poisoned with 0xAA).
// ---------------------------------------------------------------------------
__global__ void zero_kernel(float4* __restrict__ out, int n4) {
    int i = blockIdx.x * blockDim.x + threadIdx.x;
    int stride = gridDim.x * blockDim.x;
    float4 z = make_float4(0.f, 0.f, 0.f, 0.f);
    for (; i < n4; i += stride) out[i] = z;
}

// ---------------------------------------------------------------------------
__global__ void pos4_kernel(const float* __restrict__ pos, int N) {
    int i = blockIdx.x * blockDim.x + threadIdx.x;
    if (i < N)
        g_pos4[i] = make_float4(pos[3 * i], pos[3 * i + 1], pos[3 * i + 2], 0.f);
}

// ---------------------------------------------------------------------------
// Per-node precompute (fp32 math, fp16 storage). Warp per NP nodes.
// Lane owns output cols (2*lane, 2*lane+1) of all three transforms.
// ---------------------------------------------------------------------------
__global__ void node_kernel(const float* __restrict__ x,
                            const float* __restrict__ w1,
                            const float* __restrict__ b1,
                            const float* __restrict__ wt,
                            const float* __restrict__ bt,
                            int N) {
    __shared__ float sA[DIM * DIM];   // w1 rows 0..63
    __shared__ float sB[DIM * DIM];   // w1 rows 64..127
    __shared__ float sT[DIM * DIM];   // wt
    __shared__ float sb1[DIM], sbt[DIM];

    int tid = threadIdx.x;
    for (int i = tid; i < DIM * DIM; i += blockDim.x) {
        sA[i] = w1[i];
        sB[i] = w1[DIM * DIM + i];
        sT[i] = wt[i];
    }
    if (tid < DIM) { sb1[tid] = b1[tid]; sbt[tid] = bt[tid]; }
    __syncthreads();

    const int lane   = tid & 31;
    const int warp   = (blockIdx.x * blockDim.x + tid) >> 5;
    const int nwarps = (gridDim.x * blockDim.x) >> 5;
    const int NP = 4;

    float2 bb1 = *(const float2*)&sb1[2 * lane];
    float2 bbt = *(const float2*)&sbt[2 * lane];

    for (int n0 = warp * NP; n0 < N; n0 += nwarps * NP) {
        int cnt = N - n0; if (cnt > NP) cnt = NP;

        float xa[NP], xb[NP];
        #pragma unroll
        for (int j = 0; j < NP; j++) {
            int n = n0 + j;
            if (j < cnt) {
                xa[j] = x[(size_t)n * DIM + lane];
                xb[j] = x[(size_t)n * DIM + 32 + lane];
            } else { xa[j] = 0.f; xb[j] = 0.f; }
        }

        float2 au[NP], av[NP], at[NP];
        #pragma unroll
        for (int j = 0; j < NP; j++) {
            au[j] = bb1;
            av[j] = make_float2(0.f, 0.f);
            at[j] = bbt;
        }

        #pragma unroll 4
        for (int k = 0; k < DIM; k++) {
            float2 wa  = *(const float2*)&sA[k * DIM + 2 * lane];
            float2 wb  = *(const float2*)&sB[k * DIM + 2 * lane];
            float2 wt2 = *(const float2*)&sT[k * DIM + 2 * lane];
            #pragma unroll
            for (int j = 0; j < NP; j++) {
                float xk = (k < 32) ? __shfl_sync(0xffffffffu, xa[j], k)
                                    : __shfl_sync(0xffffffffu, xb[j], k - 32);
                au[j].x = fmaf(xk, wa.x,  au[j].x);
                au[j].y = fmaf(xk, wa.y,  au[j].y);
                av[j].x = fmaf(xk, wb.x,  av[j].x);
                av[j].y = fmaf(xk, wb.y,  av[j].y);
                at[j].x = fmaf(xk, wt2.x, at[j].x);
                at[j].y = fmaf(xk, wt2.y, at[j].y);
            }
        }

        #pragma unroll
        for (int j = 0; j < NP; j++) {
            if (j < cnt) {
                size_t n = (size_t)(n0 + j);
                // packed record: u pair at 8*(lane>>1) + (lane&1)*2, xt at +4
                size_t base = n * 2 * DIM + 8 * (lane >> 1) + (lane & 1) * 2;
                *(__half2*)&g_p[base]     = __float22half2_rn(au[j]);
                *(__half2*)&g_p[base + 4] = __float22half2_rn(at[j]);
                *(__half2*)&g_d[n * DIM + 2 * lane] = __float22half2_rn(av[j]);
            }
        }
    }
}

// ---------------------------------------------------------------------------
// Per-edge fused: h = relu(u[s]+v[d]+len*wc), w = sigmoid(h.w2+b2),
//   ew[e] = w, out[d] += xt[s]*w via red.global.add.v4.f32.
// HALF-warp per edge; sub (0..15) owns cols 4*sub..4*sub+3.
// Wavefront-minimized: lane-specialized index load, pos4 broadcasts,
// single LDG.128 for (u,xt).
// ---------------------------------------------------------------------------
__global__ void edge_kernel(const int* __restrict__ ei,
                            const float* __restrict__ w1,
                            const float* __restrict__ w2,
                            const float* __restrict__ b2p,
                            float* __restrict__ out,
                            float* __restrict__ ew,
                            int E) {
    const int lane   = threadIdx.x & 31;
    const int half   = lane >> 4;
    const int sub    = lane & 15;
    const int warp   = (blockIdx.x * blockDim.x + threadIdx.x) >> 5;
    const int nwarps = (gridDim.x * blockDim.x) >> 5;

    const float4 wc  = *(const float4*)&w1[128 * DIM + 4 * sub];
    const float4 w2v = *(const float4*)&w2[4 * sub];
    const float  b2  = b2p[0];

    for (int e0 = warp * 2; e0 < E; e0 += nwarps * 2) {
        // lane-specialized index load: lanes (mod 4) 0,1 -> src(e0,e0+1),
        // 2,3 -> dst(e0,e0+1). One LDG, 2 sectors, then shuffle-broadcast.
        int lidx = lane & 3;
        int addr = (lidx < 2) ? (e0 + lidx) : (E + e0 + lidx - 2);
        int val  = ei[addr];
        int s = __shfl_sync(0xffffffffu, val, half);
        int d = __shfl_sync(0xffffffffu, val, 2 + half);

        int e = e0 + half;
        bool valid = (e < E);

        float4 ps = g_pos4[s];
        float4 pd = g_pos4[d];
        float dx = pd.x - ps.x, dy = pd.y - ps.y, dz = pd.z - ps.z;
        float len = sqrtf(dx * dx + dy * dy + dz * dz);

        // one LDG.128: u pairs in .x/.y, xt pairs in .z/.w
        uint4 raw = *(const uint4*)&g_p[(size_t)s * 2 * DIM + 8 * sub];
        uint2 vraw = *(const uint2*)&g_d[(size_t)d * DIM + 4 * sub];

        float2 u0 = __half22float2(*(const __half2*)&raw.x);
        float2 u1 = __half22float2(*(const __half2*)&raw.y);
        float2 v0 = __half22float2(*(const __half2*)&vraw.x);
        float2 v1 = __half22float2(*(const __half2*)&vraw.y);

        float h0 = fmaxf(fmaf(len, wc.x, u0.x + v0.x), 0.f);
        float h1 = fmaxf(fmaf(len, wc.y, u0.y + v0.y), 0.f);
        float h2 = fmaxf(fmaf(len, wc.z, u1.x + v1.x), 0.f);
        float h3 = fmaxf(fmaf(len, wc.w, u1.y + v1.y), 0.f);
        float p  = fmaf(h0, w2v.x, fmaf(h1, w2v.y, fmaf(h2, w2v.z, h3 * w2v.w)));

        #pragma unroll
        for (int o = 8; o > 0; o >>= 1)
            p += __shfl_xor_sync(0xffffffffu, p, o);

        float w = 1.f / (1.f + __expf(-(p + b2)));

        if (valid) {
            if (sub == 0 && ew) ew[e] = w;   // lanes 0 & 16: same sector

            float2 m0 = __half22float2(*(const __half2*)&raw.z);
            float2 m1 = __half22float2(*(const __half2*)&raw.w);

            float* o0 = &out[(size_t)d * DIM + 4 * sub];
            asm volatile("red.global.add.v4.f32 [%0], {%1, %2, %3, %4};"
                         :: "l"(o0), "f"(m0.x * w), "f"(m0.y * w),
                            "f"(m1.x * w), "f"(m1.y * w)
                         : "memory");
        }
    }
}

// ---------------------------------------------------------------------------
extern "C" void kernel_launch(void* const* d_in, const int* in_sizes, int n_in,
                              void* d_out, int out_size) {
    const float* x   = (const float*)d_in[0];
    const int*   ei  = (const int*)d_in[1];    // int32 (JAX x64 disabled)
    const float* pos = (const float*)d_in[2];
    const float* w1  = (const float*)d_in[3];
    const float* b1  = (const float*)d_in[4];
    const float* w2  = (const float*)d_in[5];
    const float* b2  = (const float*)d_in[6];
    const float* wt  = (const float*)d_in[7];
    const float* bt  = (const float*)d_in[8];

    int N = in_sizes[0] / DIM;   // 100000
    int E = in_sizes[1] / 2;     // 1600000

    float* out = (float*)d_out;
    float* ew  = (out_size >= N * DIM + E) ? out + (size_t)N * DIM : nullptr;

    zero_kernel<<<592, 256>>>((float4*)out, N * DIM / 4);
    pos4_kernel<<<(N + 255) / 256, 256>>>(pos, N);
    node_kernel<<<592, 256>>>(x, w1, b1, wt, bt, N);
    edge_kernel<<<2368, 256>>>(ei, w1, w2, b2, out, ew, E);
}

// round 11
// speedup vs baseline: 1.7476x; 1.0227x over previous
#include <cuda_runtime.h>
#include <cuda_fp16.h>
#include <math.h>
#include <stdint.h>

// Scratch (static device arrays — no allocation allowed)
#define NMAX 100000
#define DIM  64

// Packed per-node src record, 128 halfs (256 B):
//   for sub in 0..15: halfs [8*sub .. 8*sub+3] = u cols 4sub..4sub+3
//                     halfs [8*sub+4 .. 8*sub+7] = xt cols 4sub..4sub+3
// -> ONE uint4 (LDG.128) per lane fetches u AND xt.
__device__ __half g_p[NMAX * 2 * DIM];
// Per-node dst record: v = x@W1b, 64 halfs (128 B).
__device__ __half g_d[NMAX * DIM];
// pos packed as float4 -> single-wavefront broadcast loads
__device__ float4 g_pos4[NMAX];

// ---------------------------------------------------------------------------
__global__ void zero_kernel(float4* __restrict__ out, int n4) {
    int i = blockIdx.x * blockDim.x + threadIdx.x;
    int stride = gridDim.x * blockDim.x;
    float4 z = make_float4(0.f, 0.f, 0.f, 0.f);
    for (; i < n4; i += stride) out[i] = z;
}

// ---------------------------------------------------------------------------
__global__ void pos4_kernel(const float* __restrict__ pos, int N) {
    int i = blockIdx.x * blockDim.x + threadIdx.x;
    if (i < N)
        g_pos4[i] = make_float4(pos[3 * i], pos[3 * i + 1], pos[3 * i + 2], 0.f);
}

// ---------------------------------------------------------------------------
// Node precompute as ONE tensor-core GEMM: Y[N x 192] = X[N x 64] @ Wc,
// Wc = [W1a | W1b | wt], bias = [b1 | 0 | bt]. tf32 mma, fp32 accumulate.
// Block: 256 thr (8 warps) x 128 rows. Warp: 16 rows x all 192 cols
// (24 n-tiles of m16n8k8, 8 k-steps). Weights staged tf32 in dyn smem,
// stride 68 (bank-conflict-free: (4n+k) mod 32 distinct).
// Epilogue: C-reg col pairs == half2 pairs -> direct packed stores.
// ---------------------------------------------------------------------------
__global__ void node_mma_kernel(const float* __restrict__ x,
                                const float* __restrict__ w1,
                                const float* __restrict__ b1,
                                const float* __restrict__ wt,
                                const float* __restrict__ bt,
                                int N) {
    extern __shared__ uint32_t sW[];          // [192][68] tf32 bits
    __shared__ float sBias[192];

    const int tid = threadIdx.x;

    // Stage W^T (col-major K for mma "row.col"): sW[n*68 + k] = tf32(Wc[k][n])
    for (int i = tid; i < 192 * 64; i += 256) {
        int n = i >> 6, k = i & 63;
        float v;
        if (n < 64)       v = w1[k * 64 + n];            // W1a
        else if (n < 128) v = w1[(64 + k) * 64 + n - 64]; // W1b
        else              v = wt[k * 64 + n - 128];       // wt
        uint32_t t;
        asm("cvt.rna.tf32.f32 %0, %1;" : "=r"(t) : "f"(v));
        sW[n * 68 + k] = t;
    }
    for (int i = tid; i < 192; i += 256)
        sBias[i] = (i < 64) ? b1[i] : ((i < 128) ? 0.f : bt[i - 128]);
    __syncthreads();

    const int warp = tid >> 5, lane = tid & 31;
    const int gid  = lane >> 2;     // group id 0..7  (row within tile)
    const int q    = lane & 3;      // thread-in-group (col quad)
    const int row0 = blockIdx.x * 128 + warp * 16;

    const int rA = row0 + gid;          // rows for c0,c1 (a0,a2)
    const int rB = row0 + gid + 8;      // rows for c2,c3 (a1,a3)
    const int rAc = rA < N ? rA : N - 1;
    const int rBc = rB < N ? rB : N - 1;

    float c[24][4];
    #pragma unroll
    for (int t = 0; t < 24; t++)
        c[t][0] = c[t][1] = c[t][2] = c[t][3] = 0.f;

    #pragma unroll
    for (int ks = 0; ks < 8; ks++) {
        int k0 = ks * 8 + q;
        float a0f = x[(size_t)rAc * 64 + k0];
        float a1f = x[(size_t)rBc * 64 + k0];
        float a2f = x[(size_t)rAc * 64 + k0 + 4];
        float a3f = x[(size_t)rBc * 64 + k0 + 4];
        uint32_t a0, a1, a2, a3;
        asm("cvt.rna.tf32.f32 %0, %1;" : "=r"(a0) : "f"(a0f));
        asm("cvt.rna.tf32.f32 %0, %1;" : "=r"(a1) : "f"(a1f));
        asm("cvt.rna.tf32.f32 %0, %1;" : "=r"(a2) : "f"(a2f));
        asm("cvt.rna.tf32.f32 %0, %1;" : "=r"(a3) : "f"(a3f));

        #pragma unroll
        for (int nt = 0; nt < 24; nt++) {
            uint32_t b0 = sW[(nt * 8 + gid) * 68 + ks * 8 + q];
            uint32_t b1r = sW[(nt * 8 + gid) * 68 + ks * 8 + q + 4];
            asm volatile(
                "mma.sync.aligned.m16n8k8.row.col.f32.tf32.tf32.f32 "
                "{%0,%1,%2,%3}, {%4,%5,%6,%7}, {%8,%9}, {%0,%1,%2,%3};"
                : "+f"(c[nt][0]), "+f"(c[nt][1]), "+f"(c[nt][2]), "+f"(c[nt][3])
                : "r"(a0), "r"(a1), "r"(a2), "r"(a3), "r"(b0), "r"(b1r));
        }
    }

    // Epilogue: col pair = (nt*8 + 2q, +1); add bias; half2 store to packed
    // layouts. Branch on nt (compile-time): nt<8 -> u in g_p, nt<16 -> v in
    // g_d, else xt in g_p (+4 offset).
    #pragma unroll
    for (int nt = 0; nt < 24; nt++) {
        int col = nt * 8 + 2 * q;
        float bb0 = sBias[col], bb1 = sBias[col + 1];

        __half2 hA = __floats2half2_rn(c[nt][0] + bb0, c[nt][1] + bb1);
        __half2 hB = __floats2half2_rn(c[nt][2] + bb0, c[nt][3] + bb1);

        if (nt < 8) {
            int cc = col;
            size_t off = 8 * (cc >> 2) + (cc & 3);
            if (rA < N) *(__half2*)&g_p[(size_t)rA * 128 + off] = hA;
            if (rB < N) *(__half2*)&g_p[(size_t)rB * 128 + off] = hB;
        } else if (nt < 16) {
            int cc = col - 64;
            if (rA < N) *(__half2*)&g_d[(size_t)rA * 64 + cc] = hA;
            if (rB < N) *(__half2*)&g_d[(size_t)rB * 64 + cc] = hB;
        } else {
            int cc = col - 128;
            size_t off = 8 * (cc >> 2) + 4 + (cc & 3);
            if (rA < N) *(__half2*)&g_p[(size_t)rA * 128 + off] = hA;
            if (rB < N) *(__half2*)&g_p[(size_t)rB * 128 + off] = hB;
        }
    }
}

// ---------------------------------------------------------------------------
// Per-edge fused: h = relu(u[s]+v[d]+len*wc), w = sigmoid(h.w2+b2),
//   ew[e] = w, out[d] += xt[s]*w via red.global.add.v4.f32.
// HALF-warp per edge; sub (0..15) owns cols 4*sub..4*sub+3.
// ---------------------------------------------------------------------------
__global__ void edge_kernel(const int* __restrict__ ei,
                            const float* __restrict__ w1,
                            const float* __restrict__ w2,
                            const float* __restrict__ b2p,
                            float* __restrict__ out,
                            float* __restrict__ ew,
                            int E) {
    const int lane   = threadIdx.x & 31;
    const int half   = lane >> 4;
    const int sub    = lane & 15;
    const int warp   = (blockIdx.x * blockDim.x + threadIdx.x) >> 5;
    const int nwarps = (gridDim.x * blockDim.x) >> 5;

    const float4 wc  = *(const float4*)&w1[128 * DIM + 4 * sub];
    const float4 w2v = *(const float4*)&w2[4 * sub];
    const float  b2  = b2p[0];

    for (int e0 = warp * 2; e0 < E; e0 += nwarps * 2) {
        // lane-specialized index load + shuffle broadcast
        int lidx = lane & 3;
        int addr = (lidx < 2) ? (e0 + lidx) : (E + e0 + lidx - 2);
        int val  = ei[addr];
        int s = __shfl_sync(0xffffffffu, val, half);
        int d = __shfl_sync(0xffffffffu, val, 2 + half);

        int e = e0 + half;
        bool valid = (e < E);

        float4 ps = g_pos4[s];
        float4 pd = g_pos4[d];
        float dx = pd.x - ps.x, dy = pd.y - ps.y, dz = pd.z - ps.z;
        float len = sqrtf(dx * dx + dy * dy + dz * dz);

        uint4 raw  = *(const uint4*)&g_p[(size_t)s * 2 * DIM + 8 * sub];
        uint2 vraw = *(const uint2*)&g_d[(size_t)d * DIM + 4 * sub];

        float2 u0 = __half22float2(*(const __half2*)&raw.x);
        float2 u1 = __half22float2(*(const __half2*)&raw.y);
        float2 v0 = __half22float2(*(const __half2*)&vraw.x);
        float2 v1 = __half22float2(*(const __half2*)&vraw.y);

        float h0 = fmaxf(fmaf(len, wc.x, u0.x + v0.x), 0.f);
        float h1 = fmaxf(fmaf(len, wc.y, u0.y + v0.y), 0.f);
        float h2 = fmaxf(fmaf(len, wc.z, u1.x + v1.x), 0.f);
        float h3 = fmaxf(fmaf(len, wc.w, u1.y + v1.y), 0.f);
        float p  = fmaf(h0, w2v.x, fmaf(h1, w2v.y, fmaf(h2, w2v.z, h3 * w2v.w)));

        #pragma unroll
        for (int o = 8; o > 0; o >>= 1)
            p += __shfl_xor_sync(0xffffffffu, p, o);

        float w = 1.f / (1.f + __expf(-(p + b2)));

        if (valid) {
            if (sub == 0 && ew) ew[e] = w;

            float2 m0 = __half22float2(*(const __half2*)&raw.z);
            float2 m1 = __half22float2(*(const __half2*)&raw.w);

            float* o0 = &out[(size_t)d * DIM + 4 * sub];
            asm volatile("red.global.add.v4.f32 [%0], {%1, %2, %3, %4};"
                         :: "l"(o0), "f"(m0.x * w), "f"(m0.y * w),
                            "f"(m1.x * w), "f"(m1.y * w)
                         : "memory");
        }
    }
}

// ---------------------------------------------------------------------------
extern "C" void kernel_launch(void* const* d_in, const int* in_sizes, int n_in,
                              void* d_out, int out_size) {
    const float* x   = (const float*)d_in[0];
    const int*   ei  = (const int*)d_in[1];    // int32 (JAX x64 disabled)
    const float* pos = (const float*)d_in[2];
    const float* w1  = (const float*)d_in[3];
    const float* b1  = (const float*)d_in[4];
    const float* w2  = (const float*)d_in[5];
    const float* b2  = (const float*)d_in[6];
    const float* wt  = (const float*)d_in[7];
    const float* bt  = (const float*)d_in[8];

    int N = in_sizes[0] / DIM;   // 100000
    int E = in_sizes[1] / 2;     // 1600000

    float* out = (float*)d_out;
    float* ew  = (out_size >= N * DIM + E) ? out + (size_t)N * DIM : nullptr;

    const int smem = 192 * 68 * 4;   // 52224 B > 48K -> opt-in
    cudaFuncSetAttribute(node_mma_kernel,
                         cudaFuncAttributeMaxDynamicSharedMemorySize, smem);

    zero_kernel<<<592, 256>>>((float4*)out, N * DIM / 4);
    pos4_kernel<<<(N + 255) / 256, 256>>>(pos, N);
    node_mma_kernel<<<(N + 127) / 128, 256, smem>>>(x, w1, b1, wt, bt, N);
    edge_kernel<<<2368, 256>>>(ei, w1, w2, b2, out, ew, E);
}

// round 12
// speedup vs baseline: 1.8171x; 1.0397x over previous
#include <cuda_runtime.h>
#include <cuda_fp16.h>
#include <math.h>
#include <stdint.h>

// Scratch (static device arrays — no allocation allowed)
#define NMAX 100000
#define DIM  64

// Packed per-node src record, 128 halfs (256 B):
//   for sub in 0..15: halfs [8*sub .. 8*sub+3] = u cols 4sub..4sub+3
//                     halfs [8*sub+4 .. 8*sub+7] = xt cols 4sub..4sub+3
// -> ONE uint4 (LDG.128) per lane fetches u AND xt.
__device__ __half g_p[NMAX * 2 * DIM];
// Per-node dst record: v = x@W1b, 64 halfs (128 B).
__device__ __half g_d[NMAX * DIM];
// pos packed as float4 -> single-wavefront broadcast loads
__device__ float4 g_pos4[NMAX];

// ---------------------------------------------------------------------------
__global__ void zero_kernel(float4* __restrict__ out, int n4) {
    int i = blockIdx.x * blockDim.x + threadIdx.x;
    int stride = gridDim.x * blockDim.x;
    float4 z = make_float4(0.f, 0.f, 0.f, 0.f);
    for (; i < n4; i += stride) out[i] = z;
}

// ---------------------------------------------------------------------------
__global__ void pos4_kernel(const float* __restrict__ pos, int N) {
    int i = blockIdx.x * blockDim.x + threadIdx.x;
    if (i < N)
        g_pos4[i] = make_float4(pos[3 * i], pos[3 * i + 1], pos[3 * i + 2], 0.f);
}

// ---------------------------------------------------------------------------
// Node precompute as ONE tensor-core GEMM: Y[N x 192] = X[N x 64] @ Wc,
// Wc = [W1a | W1b | wt], bias = [b1 | 0 | bt]. tf32 mma, fp32 accumulate.
// Block: 256 thr (8 warps) x 128 rows. Warp: 16 rows x all 192 cols
// (24 n-tiles of m16n8k8, 8 k-steps). Weights staged tf32 in dyn smem,
// stride 68 (b-reads conflict-free: (4*gid + 8*ks + q) mod 32 all distinct).
// Staging is COALESCED: consecutive threads read consecutive weight floats.
// ---------------------------------------------------------------------------
__global__ void node_mma_kernel(const float* __restrict__ x,
                                const float* __restrict__ w1,
                                const float* __restrict__ b1,
                                const float* __restrict__ wt,
                                const float* __restrict__ bt,
                                int N) {
    extern __shared__ uint32_t sW[];          // [192][68] tf32 bits
    __shared__ float sBias[192];

    const int tid = threadIdx.x;

    // Stage W^T: i = k*192 + n  ->  consecutive tid = consecutive n
    // (coalesced global reads from w1/wt rows). sW[n*68 + k] = tf32(Wc[k][n]).
    for (int i = tid; i < 192 * 64; i += 256) {
        int k = i / 192;
        int n = i - k * 192;
        float v;
        if (n < 64)       v = w1[k * 64 + n];              // W1a row k
        else if (n < 128) v = w1[(64 + k) * 64 + (n - 64)]; // W1b row k
        else              v = wt[k * 64 + (n - 128)];       // wt  row k
        uint32_t t;
        asm("cvt.rna.tf32.f32 %0, %1;" : "=r"(t) : "f"(v));
        sW[n * 68 + k] = t;
    }
    for (int i = tid; i < 192; i += 256)
        sBias[i] = (i < 64) ? b1[i] : ((i < 128) ? 0.f : bt[i - 128]);
    __syncthreads();

    const int warp = tid >> 5, lane = tid & 31;
    const int gid  = lane >> 2;     // group id 0..7  (row within tile)
    const int q    = lane & 3;      // thread-in-group (col quad)
    const int row0 = blockIdx.x * 128 + warp * 16;

    const int rA = row0 + gid;          // rows for c0,c1 (a0,a2)
    const int rB = row0 + gid + 8;      // rows for c2,c3 (a1,a3)
    const int rAc = rA < N ? rA : N - 1;
    const int rBc = rB < N ? rB : N - 1;

    float c[24][4];
    #pragma unroll
    for (int t = 0; t < 24; t++)
        c[t][0] = c[t][1] = c[t][2] = c[t][3] = 0.f;

    #pragma unroll
    for (int ks = 0; ks < 8; ks++) {
        int k0 = ks * 8 + q;
        float a0f = x[(size_t)rAc * 64 + k0];
        float a1f = x[(size_t)rBc * 64 + k0];
        float a2f = x[(size_t)rAc * 64 + k0 + 4];
        float a3f = x[(size_t)rBc * 64 + k0 + 4];
        uint32_t a0, a1, a2, a3;
        asm("cvt.rna.tf32.f32 %0, %1;" : "=r"(a0) : "f"(a0f));
        asm("cvt.rna.tf32.f32 %0, %1;" : "=r"(a1) : "f"(a1f));
        asm("cvt.rna.tf32.f32 %0, %1;" : "=r"(a2) : "f"(a2f));
        asm("cvt.rna.tf32.f32 %0, %1;" : "=r"(a3) : "f"(a3f));

        #pragma unroll
        for (int nt = 0; nt < 24; nt++) {
            uint32_t b0  = sW[(nt * 8 + gid) * 68 + ks * 8 + q];
            uint32_t b1r = sW[(nt * 8 + gid) * 68 + ks * 8 + q + 4];
            asm volatile(
                "mma.sync.aligned.m16n8k8.row.col.f32.tf32.tf32.f32 "
                "{%0,%1,%2,%3}, {%4,%5,%6,%7}, {%8,%9}, {%0,%1,%2,%3};"
                : "+f"(c[nt][0]), "+f"(c[nt][1]), "+f"(c[nt][2]), "+f"(c[nt][3])
                : "r"(a0), "r"(a1), "r"(a2), "r"(a3), "r"(b0), "r"(b1r));
        }
    }

    // Epilogue: col pair = (nt*8 + 2q, +1); add bias; half2 store to packed
    // layouts. nt<8 -> u in g_p, nt<16 -> v in g_d, else xt in g_p (+4).
    #pragma unroll
    for (int nt = 0; nt < 24; nt++) {
        int col = nt * 8 + 2 * q;
        float bb0 = sBias[col], bb1 = sBias[col + 1];

        __half2 hA = __floats2half2_rn(c[nt][0] + bb0, c[nt][1] + bb1);
        __half2 hB = __floats2half2_rn(c[nt][2] + bb0, c[nt][3] + bb1);

        if (nt < 8) {
            int cc = col;
            size_t off = 8 * (cc >> 2) + (cc & 3);
            if (rA < N) *(__half2*)&g_p[(size_t)rA * 128 + off] = hA;
            if (rB < N) *(__half2*)&g_p[(size_t)rB * 128 + off] = hB;
        } else if (nt < 16) {
            int cc = col - 64;
            if (rA < N) *(__half2*)&g_d[(size_t)rA * 64 + cc] = hA;
            if (rB < N) *(__half2*)&g_d[(size_t)rB * 64 + cc] = hB;
        } else {
            int cc = col - 128;
            size_t off = 8 * (cc >> 2) + 4 + (cc & 3);
            if (rA < N) *(__half2*)&g_p[(size_t)rA * 128 + off] = hA;
            if (rB < N) *(__half2*)&g_p[(size_t)rB * 128 + off] = hB;
        }
    }
}

// ---------------------------------------------------------------------------
// Per-edge fused: h = relu(u[s]+v[d]+len*wc), w = sigmoid(h.w2+b2),
//   ew[e] = w, out[d] += xt[s]*w via red.global.add.v4.f32.
// HALF-warp per edge; sub (0..15) owns cols 4*sub..4*sub+3.
// ---------------------------------------------------------------------------
__global__ void edge_kernel(const int* __restrict__ ei,
                            const float* __restrict__ w1,
                            const float* __restrict__ w2,
                            const float* __restrict__ b2p,
                            float* __restrict__ out,
                            float* __restrict__ ew,
                            int E) {
    const int lane   = threadIdx.x & 31;
    const int half   = lane >> 4;
    const int sub    = lane & 15;
    const int warp   = (blockIdx.x * blockDim.x + threadIdx.x) >> 5;
    const int nwarps = (gridDim.x * blockDim.x) >> 5;

    const float4 wc  = *(const float4*)&w1[128 * DIM + 4 * sub];
    const float4 w2v = *(const float4*)&w2[4 * sub];
    const float  b2  = b2p[0];

    for (int e0 = warp * 2; e0 < E; e0 += nwarps * 2) {
        // lane-specialized index load + shuffle broadcast
        int lidx = lane & 3;
        int addr = (lidx < 2) ? (e0 + lidx) : (E + e0 + lidx - 2);
        int val  = ei[addr];
        int s = __shfl_sync(0xffffffffu, val, half);
        int d = __shfl_sync(0xffffffffu, val, 2 + half);

        int e = e0 + half;
        bool valid = (e < E);

        float4 ps = g_pos4[s];
        float4 pd = g_pos4[d];
        float dx = pd.x - ps.x, dy = pd.y - ps.y, dz = pd.z - ps.z;
        float len = sqrtf(dx * dx + dy * dy + dz * dz);

        uint4 raw  = *(const uint4*)&g_p[(size_t)s * 2 * DIM + 8 * sub];
        uint2 vraw = *(const uint2*)&g_d[(size_t)d * DIM + 4 * sub];

        float2 u0 = __half22float2(*(const __half2*)&raw.x);
        float2 u1 = __half22float2(*(const __half2*)&raw.y);
        float2 v0 = __half22float2(*(const __half2*)&vraw.x);
        float2 v1 = __half22float2(*(const __half2*)&vraw.y);

        float h0 = fmaxf(fmaf(len, wc.x, u0.x + v0.x), 0.f);
        float h1 = fmaxf(fmaf(len, wc.y, u0.y + v0.y), 0.f);
        float h2 = fmaxf(fmaf(len, wc.z, u1.x + v1.x), 0.f);
        float h3 = fmaxf(fmaf(len, wc.w, u1.y + v1.y), 0.f);
        float p  = fmaf(h0, w2v.x, fmaf(h1, w2v.y, fmaf(h2, w2v.z, h3 * w2v.w)));

        #pragma unroll
        for (int o = 8; o > 0; o >>= 1)
            p += __shfl_xor_sync(0xffffffffu, p, o);

        float w = 1.f / (1.f + __expf(-(p + b2)));

        if (valid) {
            if (sub == 0 && ew) ew[e] = w;

            float2 m0 = __half22float2(*(const __half2*)&raw.z);
            float2 m1 = __half22float2(*(const __half2*)&raw.w);

            float* o0 = &out[(size_t)d * DIM + 4 * sub];
            asm volatile("red.global.add.v4.f32 [%0], {%1, %2, %3, %4};"
                         :: "l"(o0), "f"(m0.x * w), "f"(m0.y * w),
                            "f"(m1.x * w), "f"(m1.y * w)
                         : "memory");
        }
    }
}

// ---------------------------------------------------------------------------
extern "C" void kernel_launch(void* const* d_in, const int* in_sizes, int n_in,
                              void* d_out, int out_size) {
    const float* x   = (const float*)d_in[0];
    const int*   ei  = (const int*)d_in[1];    // int32 (JAX x64 disabled)
    const float* pos = (const float*)d_in[2];
    const float* w1  = (const float*)d_in[3];
    const float* b1  = (const float*)d_in[4];
    const float* w2  = (const float*)d_in[5];
    const float* b2  = (const float*)d_in[6];
    const float* wt  = (const float*)d_in[7];
    const float* bt  = (const float*)d_in[8];

    int N = in_sizes[0] / DIM;   // 100000
    int E = in_sizes[1] / 2;     // 1600000

    float* out = (float*)d_out;
    float* ew  = (out_size >= N * DIM + E) ? out + (size_t)N * DIM : nullptr;

    const int smem = 192 * 68 * 4;   // 52224 B > 48K -> opt-in
    cudaFuncSetAttribute(node_mma_kernel,
                         cudaFuncAttributeMaxDynamicSharedMemorySize, smem);

    zero_kernel<<<592, 256>>>((float4*)out, N * DIM / 4);
    pos4_kernel<<<(N + 255) / 256, 256>>>(pos, N);
    node_mma_kernel<<<(N + 127) / 128, 256, smem>>>(x, w1, b1, wt, bt, N);
    edge_kernel<<<2368, 256>>>(ei, w1, w2, b2, out, ew, E);
}

// round 13
// speedup vs baseline: 1.8304x; 1.0073x over previous
#include <cuda_runtime.h>
#include <cuda_fp16.h>
#include <math.h>
#include <stdint.h>

// Scratch (static device arrays — no allocation allowed)
#define NMAX 100000
#define DIM  64

// Packed per-node src record, 128 halfs (256 B):
//   for sub in 0..15: halfs [8*sub .. 8*sub+3] = u cols 4sub..4sub+3
//                     halfs [8*sub+4 .. 8*sub+7] = xt cols 4sub..4sub+3
// -> ONE uint4 (LDG.128) per lane fetches u AND xt.
__device__ __half g_p[NMAX * 2 * DIM];
// Per-node dst record: v = x@W1b, 64 halfs (128 B).
__device__ __half g_d[NMAX * DIM];
// pos packed as float4 -> single-wavefront broadcast loads
__device__ float4 g_pos4[NMAX];

// ---------------------------------------------------------------------------
__global__ void pos4_kernel(const float* __restrict__ pos, int N) {
    int i = blockIdx.x * blockDim.x + threadIdx.x;
    if (i < N)
        g_pos4[i] = make_float4(pos[3 * i], pos[3 * i + 1], pos[3 * i + 2], 0.f);
}

// ---------------------------------------------------------------------------
// Node precompute as ONE tensor-core GEMM: Y[N x 192] = X[N x 64] @ Wc,
// Wc = [W1a | W1b | wt], bias = [b1 | 0 | bt].
// fp16 mma m16n8k16, fp32 accumulate: half the instructions of tf32 k8 and
// the full-rate legacy HMMA shape. Weights staged as half in smem, stride 72
// halfs (36 words): b-read bank = (4*gid + 8*ks + t) mod 32, conflict-free.
// Block: 256 thr (8 warps) x 128 rows; warp: 16 rows x 192 cols
// (24 n-tiles x 4 k-steps = 96 mma).
// ---------------------------------------------------------------------------
__global__ void node_mma_kernel(const float* __restrict__ x,
                                const float* __restrict__ w1,
                                const float* __restrict__ b1,
                                const float* __restrict__ wt,
                                const float* __restrict__ bt,
                                int N) {
    __shared__ __half sW[192 * 72];      // W^T: sW[n*72 + k]
    __shared__ float  sBias[192];

    const int tid = threadIdx.x;

    // Stage W^T: i = k*192 + n -> consecutive tid = consecutive n (coalesced).
    for (int i = tid; i < 192 * 64; i += 256) {
        int k = i / 192;
        int n = i - k * 192;
        float v;
        if (n < 64)       v = w1[k * 64 + n];               // W1a row k
        else if (n < 128) v = w1[(64 + k) * 64 + (n - 64)]; // W1b row k
        else              v = wt[k * 64 + (n - 128)];       // wt  row k
        sW[n * 72 + k] = __float2half_rn(v);
    }
    for (int i = tid; i < 192; i += 256)
        sBias[i] = (i < 64) ? b1[i] : ((i < 128) ? 0.f : bt[i - 128]);
    __syncthreads();

    const int warp = tid >> 5, lane = tid & 31;
    const int gid  = lane >> 2;     // group id 0..7  (row within tile)
    const int t    = lane & 3;      // thread-in-group
    const int row0 = blockIdx.x * 128 + warp * 16;

    const int rA = row0 + gid;          // rows for c0,c1
    const int rB = row0 + gid + 8;      // rows for c2,c3
    const int rAc = rA < N ? rA : N - 1;
    const int rBc = rB < N ? rB : N - 1;

    const float2* xA = (const float2*)(x + (size_t)rAc * 64);
    const float2* xB = (const float2*)(x + (size_t)rBc * 64);

    float c[24][4];
    #pragma unroll
    for (int nt = 0; nt < 24; nt++)
        c[nt][0] = c[nt][1] = c[nt][2] = c[nt][3] = 0.f;

    #pragma unroll
    for (int ks = 0; ks < 4; ks++) {
        // A fragment (m16n8k16 row-major):
        //   a0: row gid,   k = 16ks+2t..+1     a1: row gid+8, same k
        //   a2: row gid,   k = 16ks+2t+8..+9   a3: row gid+8, same k
        int f2 = ks * 8 + t;                 // float2 index of k = 16ks+2t
        __half2 ha0 = __float22half2_rn(xA[f2]);
        __half2 ha1 = __float22half2_rn(xB[f2]);
        __half2 ha2 = __float22half2_rn(xA[f2 + 4]);
        __half2 ha3 = __float22half2_rn(xB[f2 + 4]);
        uint32_t a0 = *(uint32_t*)&ha0;
        uint32_t a1 = *(uint32_t*)&ha1;
        uint32_t a2 = *(uint32_t*)&ha2;
        uint32_t a3 = *(uint32_t*)&ha3;

        #pragma unroll
        for (int nt = 0; nt < 24; nt++) {
            // B fragment (col-major): n = nt*8+gid; b0: k=16ks+2t..+1,
            // b1: k=16ks+2t+8..+9
            const __half* bp = &sW[(nt * 8 + gid) * 72 + ks * 16 + 2 * t];
            uint32_t b0 = *(const uint32_t*)bp;
            uint32_t b1r = *(const uint32_t*)(bp + 8);
            asm volatile(
                "mma.sync.aligned.m16n8k16.row.col.f32.f16.f16.f32 "
                "{%0,%1,%2,%3}, {%4,%5,%6,%7}, {%8,%9}, {%0,%1,%2,%3};"
                : "+f"(c[nt][0]), "+f"(c[nt][1]), "+f"(c[nt][2]), "+f"(c[nt][3])
                : "r"(a0), "r"(a1), "r"(a2), "r"(a3), "r"(b0), "r"(b1r));
        }
    }

    // Epilogue: col pair = (nt*8 + 2t, +1); add bias; half2 store to packed
    // layouts. nt<8 -> u in g_p, nt<16 -> v in g_d, else xt in g_p (+4).
    #pragma unroll
    for (int nt = 0; nt < 24; nt++) {
        int col = nt * 8 + 2 * t;
        float bb0 = sBias[col], bb1 = sBias[col + 1];

        __half2 hA = __floats2half2_rn(c[nt][0] + bb0, c[nt][1] + bb1);
        __half2 hB = __floats2half2_rn(c[nt][2] + bb0, c[nt][3] + bb1);

        if (nt < 8) {
            int cc = col;
            size_t off = 8 * (cc >> 2) + (cc & 3);
            if (rA < N) *(__half2*)&g_p[(size_t)rA * 128 + off] = hA;
            if (rB < N) *(__half2*)&g_p[(size_t)rB * 128 + off] = hB;
        } else if (nt < 16) {
            int cc = col - 64;
            if (rA < N) *(__half2*)&g_d[(size_t)rA * 64 + cc] = hA;
            if (rB < N) *(__half2*)&g_d[(size_t)rB * 64 + cc] = hB;
        } else {
            int cc = col - 128;
            size_t off = 8 * (cc >> 2) + 4 + (cc & 3);
            if (rA < N) *(__half2*)&g_p[(size_t)rA * 128 + off] = hA;
            if (rB < N) *(__half2*)&g_p[(size_t)rB * 128 + off] = hB;
        }
    }
}

// ---------------------------------------------------------------------------
// Per-edge fused: h = relu(u[s]+v[d]+len*wc), w = sigmoid(h.w2+b2),
//   ew[e] = w, out[d] += xt[s]*w via red.global.add.v4.f32.
// HALF-warp per edge; sub (0..15) owns cols 4*sub..4*sub+3.
// ---------------------------------------------------------------------------
__global__ void edge_kernel(const int* __restrict__ ei,
                            const float* __restrict__ w1,
                            const float* __restrict__ w2,
                            const float* __restrict__ b2p,
                            float* __restrict__ out,
                            float* __restrict__ ew,
                            int E) {
    const int lane   = threadIdx.x & 31;
    const int half   = lane >> 4;
    const int sub    = lane & 15;
    const int warp   = (blockIdx.x * blockDim.x + threadIdx.x) >> 5;
    const int nwarps = (gridDim.x * blockDim.x) >> 5;

    const float4 wc  = *(const float4*)&w1[128 * DIM + 4 * sub];
    const float4 w2v = *(const float4*)&w2[4 * sub];
    const float  b2  = b2p[0];

    for (int e0 = warp * 2; e0 < E; e0 += nwarps * 2) {
        // lane-specialized index load + shuffle broadcast
        int lidx = lane & 3;
        int addr = (lidx < 2) ? (e0 + lidx) : (E + e0 + lidx - 2);
        int val  = ei[addr];
        int s = __shfl_sync(0xffffffffu, val, half);
        int d = __shfl_sync(0xffffffffu, val, 2 + half);

        int e = e0 + half;
        bool valid = (e < E);

        float4 ps = g_pos4[s];
        float4 pd = g_pos4[d];
        float dx = pd.x - ps.x, dy = pd.y - ps.y, dz = pd.z - ps.z;
        float len = sqrtf(dx * dx + dy * dy + dz * dz);

        uint4 raw  = *(const uint4*)&g_p[(size_t)s * 2 * DIM + 8 * sub];
        uint2 vraw = *(const uint2*)&g_d[(size_t)d * DIM + 4 * sub];

        float2 u0 = __half22float2(*(const __half2*)&raw.x);
        float2 u1 = __half22float2(*(const __half2*)&raw.y);
        float2 v0 = __half22float2(*(const __half2*)&vraw.x);
        float2 v1 = __half22float2(*(const __half2*)&vraw.y);

        float h0 = fmaxf(fmaf(len, wc.x, u0.x + v0.x), 0.f);
        float h1 = fmaxf(fmaf(len, wc.y, u0.y + v0.y), 0.f);
        float h2 = fmaxf(fmaf(len, wc.z, u1.x + v1.x), 0.f);
        float h3 = fmaxf(fmaf(len, wc.w, u1.y + v1.y), 0.f);
        float p  = fmaf(h0, w2v.x, fmaf(h1, w2v.y, fmaf(h2, w2v.z, h3 * w2v.w)));

        #pragma unroll
        for (int o = 8; o > 0; o >>= 1)
            p += __shfl_xor_sync(0xffffffffu, p, o);

        float w = 1.f / (1.f + __expf(-(p + b2)));

        if (valid) {
            if (sub == 0 && ew) ew[e] = w;

            float2 m0 = __half22float2(*(const __half2*)&raw.z);
            float2 m1 = __half22float2(*(const __half2*)&raw.w);

            float* o0 = &out[(size_t)d * DIM + 4 * sub];
            asm volatile("red.global.add.v4.f32 [%0], {%1, %2, %3, %4};"
                         :: "l"(o0), "f"(m0.x * w), "f"(m0.y * w),
                            "f"(m1.x * w), "f"(m1.y * w)
                         : "memory");
        }
    }
}

// ---------------------------------------------------------------------------
extern "C" void kernel_launch(void* const* d_in, const int* in_sizes, int n_in,
                              void* d_out, int out_size) {
    const float* x   = (const float*)d_in[0];
    const int*   ei  = (const int*)d_in[1];    // int32 (JAX x64 disabled)
    const float* pos = (const float*)d_in[2];
    const float* w1  = (const float*)d_in[3];
    const float* b1  = (const float*)d_in[4];
    const float* w2  = (const float*)d_in[5];
    const float* b2  = (const float*)d_in[6];
    const float* wt  = (const float*)d_in[7];
    const float* bt  = (const float*)d_in[8];

    int N = in_sizes[0] / DIM;   // 100000
    int E = in_sizes[1] / 2;     // 1600000

    float* out = (float*)d_out;
    float* ew  = (out_size >= N * DIM + E) ? out + (size_t)N * DIM : nullptr;

    // zero only the node-output region (ew region fully overwritten)
    cudaMemsetAsync(out, 0, (size_t)N * DIM * sizeof(float));

    pos4_kernel<<<(N + 255) / 256, 256>>>(pos, N);
    node_mma_kernel<<<(N + 127) / 128, 256>>>(x, w1, b1, wt, bt, N);
    edge_kernel<<<2368, 256>>>(ei, w1, w2, b2, out, ew, E);
}

// round 14
// speedup vs baseline: 1.9952x; 1.0900x over previous
#include <cuda_runtime.h>
#include <cuda_fp16.h>
#include <math.h>
#include <stdint.h>

// Scratch (static device arrays — no allocation allowed)
#define NMAX 100000
#define DIM  64

// Packed per-node src record, 128 halfs (256 B):
//   for sub in 0..15: halfs [8*sub .. 8*sub+3] = u cols 4sub..4sub+3
//                     halfs [8*sub+4 .. 8*sub+7] = xt cols 4sub..4sub+3
// -> ONE uint4 (LDG.128) per lane fetches u AND xt.
__device__ __half g_p[NMAX * 2 * DIM];
// Per-node dst record: v = x@W1b, 64 halfs (128 B).
__device__ __half g_d[NMAX * DIM];
// pos packed as float4 -> single-wavefront broadcast loads
__device__ float4 g_pos4[NMAX];

// ---------------------------------------------------------------------------
__global__ void pos4_kernel(const float* __restrict__ pos, int N) {
    int i = blockIdx.x * blockDim.x + threadIdx.x;
    if (i < N)
        g_pos4[i] = make_float4(pos[3 * i], pos[3 * i + 1], pos[3 * i + 2], 0.f);
}

// ---------------------------------------------------------------------------
// Node precompute GEMM: Y[N x 192] = X[N x 64] @ [W1a|W1b|wt], + bias.
// fp16 mma m16n8k16, fp32 accum. CHUNKED over n: 3 chunks x 8 n-tiles with
// c[8][4] (32 accum regs) and per-chunk epilogue; A-fragments hoisted
// (16 regs). Live regs ~80 -> no spill, multi-block occupancy.
// Weights staged as half, stride 72 halfs (conflict-free b-reads).
// ---------------------------------------------------------------------------
__global__ void node_mma_kernel(const float* __restrict__ x,
                                const float* __restrict__ w1,
                                const float* __restrict__ b1,
                                const float* __restrict__ wt,
                                const float* __restrict__ bt,
                                int N) {
    __shared__ __half sW[192 * 72];      // W^T: sW[n*72 + k]
    __shared__ float  sBias[192];

    const int tid = threadIdx.x;

    // Stage W^T: i = k*192 + n -> consecutive tid = consecutive n (coalesced).
    for (int i = tid; i < 192 * 64; i += 256) {
        int k = i / 192;
        int n = i - k * 192;
        float v;
        if (n < 64)       v = w1[k * 64 + n];               // W1a row k
        else if (n < 128) v = w1[(64 + k) * 64 + (n - 64)]; // W1b row k
        else              v = wt[k * 64 + (n - 128)];       // wt  row k
        sW[n * 72 + k] = __float2half_rn(v);
    }
    for (int i = tid; i < 192; i += 256)
        sBias[i] = (i < 64) ? b1[i] : ((i < 128) ? 0.f : bt[i - 128]);
    __syncthreads();

    const int warp = tid >> 5, lane = tid & 31;
    const int gid  = lane >> 2;     // group id 0..7  (row within tile)
    const int t    = lane & 3;      // thread-in-group
    const int row0 = blockIdx.x * 128 + warp * 16;

    const int rA = row0 + gid;          // rows for c0,c1
    const int rB = row0 + gid + 8;      // rows for c2,c3
    const int rAc = rA < N ? rA : N - 1;
    const int rBc = rB < N ? rB : N - 1;

    const float2* xA = (const float2*)(x + (size_t)rAc * 64);
    const float2* xB = (const float2*)(x + (size_t)rBc * 64);

    // Hoisted A fragments: a[ks][0..3]
    uint32_t a[4][4];
    #pragma unroll
    for (int ks = 0; ks < 4; ks++) {
        int f2 = ks * 8 + t;
        __half2 h0 = __float22half2_rn(xA[f2]);
        __half2 h1 = __float22half2_rn(xB[f2]);
        __half2 h2 = __float22half2_rn(xA[f2 + 4]);
        __half2 h3 = __float22half2_rn(xB[f2 + 4]);
        a[ks][0] = *(uint32_t*)&h0;
        a[ks][1] = *(uint32_t*)&h1;
        a[ks][2] = *(uint32_t*)&h2;
        a[ks][3] = *(uint32_t*)&h3;
    }

    #pragma unroll
    for (int chunk = 0; chunk < 3; chunk++) {
        float c[8][4];
        #pragma unroll
        for (int j = 0; j < 8; j++)
            c[j][0] = c[j][1] = c[j][2] = c[j][3] = 0.f;

        #pragma unroll
        for (int ks = 0; ks < 4; ks++) {
            #pragma unroll
            for (int j = 0; j < 8; j++) {
                int nt = chunk * 8 + j;
                const __half* bp = &sW[(nt * 8 + gid) * 72 + ks * 16 + 2 * t];
                uint32_t b0  = *(const uint32_t*)bp;
                uint32_t b1r = *(const uint32_t*)(bp + 8);
                asm volatile(
                    "mma.sync.aligned.m16n8k16.row.col.f32.f16.f16.f32 "
                    "{%0,%1,%2,%3}, {%4,%5,%6,%7}, {%8,%9}, {%0,%1,%2,%3};"
                    : "+f"(c[j][0]), "+f"(c[j][1]), "+f"(c[j][2]), "+f"(c[j][3])
                    : "r"(a[ks][0]), "r"(a[ks][1]), "r"(a[ks][2]), "r"(a[ks][3]),
                      "r"(b0), "r"(b1r));
            }
        }

        // Per-chunk epilogue. chunk0 -> u in g_p, chunk1 -> v in g_d,
        // chunk2 -> xt in g_p (+4 offset). col = nt*8 + 2t.
        #pragma unroll
        for (int j = 0; j < 8; j++) {
            int nt  = chunk * 8 + j;
            int col = nt * 8 + 2 * t;
            float bb0 = sBias[col], bb1 = sBias[col + 1];

            __half2 hA = __floats2half2_rn(c[j][0] + bb0, c[j][1] + bb1);
            __half2 hB = __floats2half2_rn(c[j][2] + bb0, c[j][3] + bb1);

            if (chunk == 0) {
                int cc = col;
                size_t off = 8 * (cc >> 2) + (cc & 3);
                if (rA < N) *(__half2*)&g_p[(size_t)rA * 128 + off] = hA;
                if (rB < N) *(__half2*)&g_p[(size_t)rB * 128 + off] = hB;
            } else if (chunk == 1) {
                int cc = col - 64;
                if (rA < N) *(__half2*)&g_d[(size_t)rA * 64 + cc] = hA;
                if (rB < N) *(__half2*)&g_d[(size_t)rB * 64 + cc] = hB;
            } else {
                int cc = col - 128;
                size_t off = 8 * (cc >> 2) + 4 + (cc & 3);
                if (rA < N) *(__half2*)&g_p[(size_t)rA * 128 + off] = hA;
                if (rB < N) *(__half2*)&g_p[(size_t)rB * 128 + off] = hB;
            }
        }
    }
}

// ---------------------------------------------------------------------------
// Per-edge fused: h = relu(u[s]+v[d]+len*wc), w = sigmoid(h.w2+b2),
//   ew[e] = w, out[d] += xt[s]*w via red.global.add.v4.f32.
// HALF-warp per edge; sub (0..15) owns cols 4*sub..4*sub+3.
// ---------------------------------------------------------------------------
__global__ void edge_kernel(const int* __restrict__ ei,
                            const float* __restrict__ w1,
                            const float* __restrict__ w2,
                            const float* __restrict__ b2p,
                            float* __restrict__ out,
                            float* __restrict__ ew,
                            int E) {
    const int lane   = threadIdx.x & 31;
    const int half   = lane >> 4;
    const int sub    = lane & 15;
    const int warp   = (blockIdx.x * blockDim.x + threadIdx.x) >> 5;
    const int nwarps = (gridDim.x * blockDim.x) >> 5;

    const float4 wc  = *(const float4*)&w1[128 * DIM + 4 * sub];
    const float4 w2v = *(const float4*)&w2[4 * sub];
    const float  b2  = b2p[0];

    for (int e0 = warp * 2; e0 < E; e0 += nwarps * 2) {
        // lane-specialized index load + shuffle broadcast
        int lidx = lane & 3;
        int addr = (lidx < 2) ? (e0 + lidx) : (E + e0 + lidx - 2);
        int val  = ei[addr];
        int s = __shfl_sync(0xffffffffu, val, half);
        int d = __shfl_sync(0xffffffffu, val, 2 + half);

        int e = e0 + half;
        bool valid = (e < E);

        float4 ps = g_pos4[s];
        float4 pd = g_pos4[d];
        float dx = pd.x - ps.x, dy = pd.y - ps.y, dz = pd.z - ps.z;
        float len = sqrtf(dx * dx + dy * dy + dz * dz);

        uint4 raw  = *(const uint4*)&g_p[(size_t)s * 2 * DIM + 8 * sub];
        uint2 vraw = *(const uint2*)&g_d[(size_t)d * DIM + 4 * sub];

        float2 u0 = __half22float2(*(const __half2*)&raw.x);
        float2 u1 = __half22float2(*(const __half2*)&raw.y);
        float2 v0 = __half22float2(*(const __half2*)&vraw.x);
        float2 v1 = __half22float2(*(const __half2*)&vraw.y);

        float h0 = fmaxf(fmaf(len, wc.x, u0.x + v0.x), 0.f);
        float h1 = fmaxf(fmaf(len, wc.y, u0.y + v0.y), 0.f);
        float h2 = fmaxf(fmaf(len, wc.z, u1.x + v1.x), 0.f);
        float h3 = fmaxf(fmaf(len, wc.w, u1.y + v1.y), 0.f);
        float p  = fmaf(h0, w2v.x, fmaf(h1, w2v.y, fmaf(h2, w2v.z, h3 * w2v.w)));

        #pragma unroll
        for (int o = 8; o > 0; o >>= 1)
            p += __shfl_xor_sync(0xffffffffu, p, o);

        float w = 1.f / (1.f + __expf(-(p + b2)));

        if (valid) {
            if (sub == 0 && ew) ew[e] = w;

            float2 m0 = __half22float2(*(const __half2*)&raw.z);
            float2 m1 = __half22float2(*(const __half2*)&raw.w);

            float* o0 = &out[(size_t)d * DIM + 4 * sub];
            asm volatile("red.global.add.v4.f32 [%0], {%1, %2, %3, %4};"
                         :: "l"(o0), "f"(m0.x * w), "f"(m0.y * w),
                            "f"(m1.x * w), "f"(m1.y * w)
                         : "memory");
        }
    }
}

// ---------------------------------------------------------------------------
extern "C" void kernel_launch(void* const* d_in, const int* in_sizes, int n_in,
                              void* d_out, int out_size) {
    const float* x   = (const float*)d_in[0];
    const int*   ei  = (const int*)d_in[1];    // int32 (JAX x64 disabled)
    const float* pos = (const float*)d_in[2];
    const float* w1  = (const float*)d_in[3];
    const float* b1  = (const float*)d_in[4];
    const float* w2  = (const float*)d_in[5];
    const float* b2  = (const float*)d_in[6];
    const float* wt  = (const float*)d_in[7];
    const float* bt  = (const float*)d_in[8];

    int N = in_sizes[0] / DIM;   // 100000
    int E = in_sizes[1] / 2;     // 1600000

    float* out = (float*)d_out;
    float* ew  = (out_size >= N * DIM + E) ? out + (size_t)N * DIM : nullptr;

    // zero only the node-output region (ew region fully overwritten)
    cudaMemsetAsync(out, 0, (size_t)N * DIM * sizeof(float));

    // node_mma at launch index 1: ncu -s 5 (period 4) lands here next round
    node_mma_kernel<<<(N + 127) / 128, 256>>>(x, w1, b1, wt, bt, N);
    pos4_kernel<<<(N + 255) / 256, 256>>>(pos, N);
    edge_kernel<<<2368, 256>>>(ei, w1, w2, b2, out, ew, E);
}